// round 3
// baseline (speedup 1.0000x reference)
#include <cuda_runtime.h>
#include <cstdint>

#define BATCH 64
#define NSPEC 8
#define VOCAB 128000
#define ROWS (BATCH * NSPEC)
#define THREADS_ARGMAX 256
#define VEC_PER_ROW (VOCAB / 4)               // 32000
#define ITERS (VEC_PER_ROW / THREADS_ARGMAX)  // 125 exact

// Scratch: argmax token per (batch, spec) row. __device__ global (no alloc).
__device__ int g_tgt[ROWS];

// Monotone order-preserving mapping fp32 -> u32 (no NaNs in input).
__device__ __forceinline__ unsigned ford(float f) {
    unsigned u = __float_as_uint(f);
    return u ^ ((unsigned)((int)u >> 31) | 0x80000000u);
}

// One CTA per row: vectorized streaming argmax with first-index tie-break.
__global__ void __launch_bounds__(THREADS_ARGMAX, 4)
argmax_kernel(const float* __restrict__ logits) {
    const int row = blockIdx.x;
    const float4* __restrict__ p =
        reinterpret_cast<const float4*>(logits + (size_t)row * VOCAB);

    float best = -3.402823466e+38f;
    int bidx = 0;
    int k = threadIdx.x;
#pragma unroll 5
    for (int it = 0; it < ITERS; ++it, k += THREADS_ARGMAX) {
        float4 v = __ldcs(&p[k]);   // read-once stream: evict-first, keep L2 clean
        float m01 = fmaxf(v.x, v.y);
        float m23 = fmaxf(v.z, v.w);
        float m = fmaxf(m01, m23);
        if (m > best) {            // strict > : earliest index wins in-thread
            best = m;
            int base = k * 4;
            bidx = (v.x == m) ? base
                 : (v.y == m) ? base + 1
                 : (v.z == m) ? base + 2
                 : base + 3;
        }
    }

    // Pack (value, ~idx): u64 max == (max value, then smallest index).
    unsigned long long key =
        ((unsigned long long)ford(best) << 32) |
        (unsigned long long)(0xFFFFFFFFu - (unsigned)bidx);

#pragma unroll
    for (int off = 16; off > 0; off >>= 1) {
        unsigned long long o = __shfl_down_sync(0xFFFFFFFFu, key, off);
        key = (o > key) ? o : key;
    }
    __shared__ unsigned long long s_key[THREADS_ARGMAX / 32];
    if ((threadIdx.x & 31) == 0) s_key[threadIdx.x >> 5] = key;
    __syncthreads();
    if (threadIdx.x < (THREADS_ARGMAX / 32)) {
        key = s_key[threadIdx.x];
#pragma unroll
        for (int off = (THREADS_ARGMAX / 64); off > 0; off >>= 1) {
            unsigned long long o = __shfl_down_sync(0xFFu, key, off);
            key = (o > key) ? o : key;
        }
        if (threadIdx.x == 0)
            g_tgt[row] = (int)(0xFFFFFFFFu - (unsigned)(key & 0xFFFFFFFFull));
    }
}

// One thread per batch row. Detects int64 vs int32 INPUT token dtype at
// runtime (deterministic for fixed inputs). OUTPUT is written as float32:
// the harness's single __output__ dtype is floating point (round-1 evidence:
// int-bit writes of -1 decoded as NaN), and all values (< 2^24) are exact.
__global__ void __launch_bounds__(64)
finalize_kernel(const void* __restrict__ draft_raw,
                const void* __restrict__ bonus_raw,
                float* __restrict__ out) {
    __shared__ int s_not64;
    if (threadIdx.x == 0) s_not64 = 0;
    __syncthreads();

    // First 2048 bytes of draft buffer exist under either dtype
    // (512*int32 = 2048 B; 512*int64 = 4096 B). If int64, every high word
    // is 0 (tokens in [0,128000)); if int32, odd tokens occupy high words.
    const unsigned long long* d64chk = (const unsigned long long*)draft_raw;
    for (int j = threadIdx.x; j < 256; j += 64)
        if (d64chk[j] >> 32) atomicOr(&s_not64, 1);
    __syncthreads();
    const bool is64 = (s_not64 == 0);

    const int b = threadIdx.x;
    if (b >= BATCH) return;

    const long long* draft64 = (const long long*)draft_raw;
    const int*       draft32 = (const int*)draft_raw;
    const long long* bonus64 = (const long long*)bonus_raw;
    const int*       bonus32 = (const int*)bonus_raw;

    int tgt[NSPEC];
    bool eq[NSPEC];
    int cum = 0;
#pragma unroll
    for (int s = 0; s < NSPEC; ++s) {
        tgt[s] = g_tgt[b * NSPEC + s];
        long long dv = is64 ? draft64[b * NSPEC + s]
                            : (long long)draft32[b * NSPEC + s];
        cum += (dv == (long long)tgt[s]) ? 1 : 0;
        eq[s] = ((cum - 1) == s);   // true iff drafts 0..s all matched
    }

    int sum_eq = 0;
#pragma unroll
    for (int s = 0; s < NSPEC; ++s) sum_eq += eq[s] ? 1 : 0;
    const int num_rejected = NSPEC - sum_eq;

    // jnp.argmin over eq (int): first False index, or 0 if all True.
    int first_diff = 0;
    bool any_false = false;
#pragma unroll
    for (int s = 0; s < NSPEC; ++s) {
        if (!any_false && !eq[s]) { first_diff = s; any_false = true; }
    }
    if (!any_false) first_diff = 0;

    float outrow[NSPEC + 1];
    int keep_count = 0;
#pragma unroll
    for (int s = 0; s < NSPEC; ++s) {
        bool keep = (s <= first_diff) || eq[s];
        outrow[s] = keep ? (float)tgt[s] : -1.0f;
        keep_count += keep ? 1 : 0;
    }
    const bool last_all = eq[NSPEC - 1];
    long long bonus = is64 ? bonus64[b] : (long long)bonus32[b];
    outrow[NSPEC] = last_all ? (float)bonus : -1.0f;
    keep_count += last_all ? 1 : 0;

    const float last_tok = outrow[keep_count - 1];

    // Flattened tuple layout: [64*9 tokens | 64 num_rejected | 64 last_token]
#pragma unroll
    for (int s = 0; s <= NSPEC; ++s)
        out[b * (NSPEC + 1) + s] = outrow[s];
    out[BATCH * (NSPEC + 1) + b]         = (float)num_rejected;
    out[BATCH * (NSPEC + 1) + BATCH + b] = last_tok;
}

extern "C" void kernel_launch(void* const* d_in, const int* in_sizes, int n_in,
                              void* d_out, int out_size) {
    const float* logits = (const float*)d_in[0];   // [64, 8, 128000] fp32
    const void*  draft  = d_in[1];                 // [64, 8] int64 or int32
    const void*  bonus  = d_in[2];                 // [64, 1] int64 or int32
    (void)in_sizes; (void)n_in; (void)out_size;

    argmax_kernel<<<ROWS, THREADS_ARGMAX>>>(logits);
    finalize_kernel<<<1, 64>>>(draft, bonus, (float*)d_out);
}

// round 6
// speedup vs baseline: 1.0907x; 1.0907x over previous
#include <cuda_runtime.h>
#include <cstdint>

#define BATCH 64
#define NSPEC 8
#define VOCAB 128000
#define ROWS (BATCH * NSPEC)
#define NTHREADS 256
#define VEC_PER_ROW (VOCAB / 4)      // 32000
#define UNROLL 5
#define BLOCKS_PER_THREAD 25         // 25 * 5 * 256 = 32000 exact

// Scratch (device globals, allocation-free, zero-initialized at load).
__device__ int g_tgt[ROWS];
__device__ unsigned g_count;

// Monotone order-preserving fp32 -> u32 (no NaNs in input).
__device__ __forceinline__ unsigned ford(float f) {
    unsigned u = __float_as_uint(f);
    return u ^ ((unsigned)((int)u >> 31) | 0x80000000u);
}

// Single fused kernel: per-row argmax (512 CTAs) + last-CTA rejection epilogue.
__global__ void __launch_bounds__(NTHREADS, 4)
fused_kernel(const float* __restrict__ logits,
             const void* __restrict__ draft_raw,
             const void* __restrict__ bonus_raw,
             float* __restrict__ out) {
    const int row = blockIdx.x;
    const float4* __restrict__ p =
        reinterpret_cast<const float4*>(logits + (size_t)row * VOCAB);

    // ---- streaming block-max with deferred index recovery ----
    float best = -3.402823466e+38f;
    int kbest = 0;                    // base vec index of winning 5-block
    int k = threadIdx.x;
#pragma unroll 1
    for (int it = 0; it < BLOCKS_PER_THREAD; ++it) {
        float4 v0 = __ldcs(&p[k]);
        float4 v1 = __ldcs(&p[k + NTHREADS]);
        float4 v2 = __ldcs(&p[k + 2 * NTHREADS]);
        float4 v3 = __ldcs(&p[k + 3 * NTHREADS]);
        float4 v4 = __ldcs(&p[k + 4 * NTHREADS]);
        float m0 = fmaxf(fmaxf(v0.x, v0.y), fmaxf(v0.z, v0.w));
        float m1 = fmaxf(fmaxf(v1.x, v1.y), fmaxf(v1.z, v1.w));
        float m2 = fmaxf(fmaxf(v2.x, v2.y), fmaxf(v2.z, v2.w));
        float m3 = fmaxf(fmaxf(v3.x, v3.y), fmaxf(v3.z, v3.w));
        float m4 = fmaxf(fmaxf(v4.x, v4.y), fmaxf(v4.z, v4.w));
        float bm = fmaxf(fmaxf(fmaxf(m0, m1), fmaxf(m2, m3)), m4);
        if (bm > best) { best = bm; kbest = k; }   // strict >: earliest block
        k += UNROLL * NTHREADS;
    }

    // Recover exact index: re-read the winning block, first match wins.
    int bidx = 0;
    bool found = false;
#pragma unroll
    for (int u = 0; u < UNROLL; ++u) {
        float4 v = p[kbest + u * NTHREADS];
        int base = (kbest + u * NTHREADS) * 4;
        if (!found && v.x == best) { bidx = base;     found = true; }
        if (!found && v.y == best) { bidx = base + 1; found = true; }
        if (!found && v.z == best) { bidx = base + 2; found = true; }
        if (!found && v.w == best) { bidx = base + 3; found = true; }
    }

    // Pack (value, ~idx): u64 max == (max value, then smallest index).
    unsigned long long key =
        ((unsigned long long)ford(best) << 32) |
        (unsigned long long)(0xFFFFFFFFu - (unsigned)bidx);

#pragma unroll
    for (int off = 16; off > 0; off >>= 1) {
        unsigned long long o = __shfl_down_sync(0xFFFFFFFFu, key, off);
        key = (o > key) ? o : key;
    }
    __shared__ unsigned long long s_key[NTHREADS / 32];
    __shared__ int s_last;
    __shared__ int s_not64;
    if ((threadIdx.x & 31) == 0) s_key[threadIdx.x >> 5] = key;
    __syncthreads();
    if (threadIdx.x < (NTHREADS / 32)) {
        key = s_key[threadIdx.x];
#pragma unroll
        for (int off = (NTHREADS / 64); off > 0; off >>= 1) {
            unsigned long long o = __shfl_down_sync(0xFFu, key, off);
            key = (o > key) ? o : key;
        }
        if (threadIdx.x == 0)
            g_tgt[row] = (int)(0xFFFFFFFFu - (unsigned)(key & 0xFFFFFFFFull));
    }

    // ---- last-CTA-done handoff ----
    if (threadIdx.x == 0) {
        __threadfence();                       // release g_tgt[row]
        unsigned t = atomicAdd(&g_count, 1u);
        s_last = (t == (unsigned)(gridDim.x - 1));
        s_not64 = 0;
    }
    __syncthreads();
    if (!s_last) return;
    __threadfence();                           // acquire all g_tgt writes

    // ---- rejection-sampling epilogue (threads 0..63, one per batch row) ----
    // Input token dtype detected at runtime: first 2048 B of draft exist under
    // either dtype; int64 => every high word 0 (tokens < 128000).
    const unsigned long long* d64chk = (const unsigned long long*)draft_raw;
    for (int j = threadIdx.x; j < 256; j += NTHREADS)
        if (d64chk[j] >> 32) atomicOr(&s_not64, 1);
    __syncthreads();
    const bool is64 = (s_not64 == 0);

    const int b = threadIdx.x;
    if (b < BATCH) {
        const long long* draft64 = (const long long*)draft_raw;
        const int*       draft32 = (const int*)draft_raw;
        const long long* bonus64 = (const long long*)bonus_raw;
        const int*       bonus32 = (const int*)bonus_raw;

        int tgt[NSPEC];
        bool eq[NSPEC];
        int cum = 0;
#pragma unroll
        for (int s = 0; s < NSPEC; ++s) {
            tgt[s] = g_tgt[b * NSPEC + s];
            long long dv = is64 ? draft64[b * NSPEC + s]
                                : (long long)draft32[b * NSPEC + s];
            cum += (dv == (long long)tgt[s]) ? 1 : 0;
            eq[s] = ((cum - 1) == s);          // drafts 0..s all matched
        }

        int sum_eq = 0;
#pragma unroll
        for (int s = 0; s < NSPEC; ++s) sum_eq += eq[s] ? 1 : 0;
        const int num_rejected = NSPEC - sum_eq;

        int first_diff = 0;                    // jnp.argmin: first False, else 0
        bool any_false = false;
#pragma unroll
        for (int s = 0; s < NSPEC; ++s)
            if (!any_false && !eq[s]) { first_diff = s; any_false = true; }

        float outrow[NSPEC + 1];
        int keep_count = 0;
#pragma unroll
        for (int s = 0; s < NSPEC; ++s) {
            bool keep = (s <= first_diff) || eq[s];
            outrow[s] = keep ? (float)tgt[s] : -1.0f;
            keep_count += keep ? 1 : 0;
        }
        const bool last_all = eq[NSPEC - 1];
        long long bonus = is64 ? bonus64[b] : (long long)bonus32[b];
        outrow[NSPEC] = last_all ? (float)bonus : -1.0f;
        keep_count += last_all ? 1 : 0;

        const float last_tok = outrow[keep_count - 1];

        // Flattened tuple: [64*9 tokens | 64 num_rejected | 64 last_token]
#pragma unroll
        for (int s = 0; s <= NSPEC; ++s)
            out[b * (NSPEC + 1) + s] = outrow[s];
        out[BATCH * (NSPEC + 1) + b]         = (float)num_rejected;
        out[BATCH * (NSPEC + 1) + BATCH + b] = last_tok;
    }

    __syncthreads();
    if (threadIdx.x == 0) g_count = 0;         // reset for next graph replay
}

extern "C" void kernel_launch(void* const* d_in, const int* in_sizes, int n_in,
                              void* d_out, int out_size) {
    const float* logits = (const float*)d_in[0];   // [64, 8, 128000] fp32
    const void*  draft  = d_in[1];                 // [64, 8] int64 or int32
    const void*  bonus  = d_in[2];                 // [64, 1] int64 or int32
    (void)in_sizes; (void)n_in; (void)out_size;

    fused_kernel<<<ROWS, NTHREADS>>>(logits, draft, bonus, (float*)d_out);
}

// round 8
// speedup vs baseline: 1.1076x; 1.0155x over previous
#include <cuda_runtime.h>
#include <cstdint>

#define BATCH 64
#define NSPEC 8
#define VOCAB 128000
#define ROWS (BATCH * NSPEC)
#define SEGS_PER_ROW 2
#define NPART (ROWS * SEGS_PER_ROW)        // 1024 partials
#define NTHREADS 128
#define VEC_PER_SEG (VOCAB / 4 / SEGS_PER_ROW)   // 16000
#define UNROLL 5
#define BLOCKS_PER_THREAD 25               // 25 * 5 * 128 = 16000 exact
#define STRIDE NTHREADS

// Scratch (device globals, allocation-free).
__device__ unsigned long long g_part[NPART];
__device__ unsigned g_count;

// Monotone order-preserving fp32 -> u32 (no NaNs in input).
__device__ __forceinline__ unsigned ford(float f) {
    unsigned u = __float_as_uint(f);
    return u ^ ((unsigned)((int)u >> 31) | 0x80000000u);
}

__device__ __forceinline__ float max4(float4 v) {
    return fmaxf(fmaxf(v.x, v.y), fmaxf(v.z, v.w));
}

// 1024 CTAs: (row, half-row segment) partial argmax + last-CTA epilogue.
__global__ void __launch_bounds__(NTHREADS, 8)
fused_kernel(const float* __restrict__ logits,
             const void* __restrict__ draft_raw,
             const void* __restrict__ bonus_raw,
             float* __restrict__ out) {
    const int row = blockIdx.x >> 1;
    const int seg = blockIdx.x & 1;
    const float4* __restrict__ p =
        reinterpret_cast<const float4*>(logits + (size_t)row * VOCAB);
    const int seg_base = seg * VEC_PER_SEG;

    // ---- software-pipelined streaming block-max (10 LDG.128 in flight) ----
    float best = -3.402823466e+38f;
    int kbest = seg_base + threadIdx.x;
    int kcur = seg_base + threadIdx.x;

    float4 v0 = __ldcs(&p[kcur]);
    float4 v1 = __ldcs(&p[kcur + STRIDE]);
    float4 v2 = __ldcs(&p[kcur + 2 * STRIDE]);
    float4 v3 = __ldcs(&p[kcur + 3 * STRIDE]);
    float4 v4 = __ldcs(&p[kcur + 4 * STRIDE]);

#pragma unroll 1
    for (int it = 0; it < BLOCKS_PER_THREAD - 1; ++it) {
        const int knext = kcur + UNROLL * STRIDE;
        // prefetch next block (front-batched, overlaps the tree below)
        float4 w0 = __ldcs(&p[knext]);
        float4 w1 = __ldcs(&p[knext + STRIDE]);
        float4 w2 = __ldcs(&p[knext + 2 * STRIDE]);
        float4 w3 = __ldcs(&p[knext + 3 * STRIDE]);
        float4 w4 = __ldcs(&p[knext + 4 * STRIDE]);
        float bm = fmaxf(fmaxf(fmaxf(max4(v0), max4(v1)),
                               fmaxf(max4(v2), max4(v3))), max4(v4));
        if (bm > best) { best = bm; kbest = kcur; }  // strict >: earliest block
        v0 = w0; v1 = w1; v2 = w2; v3 = w3; v4 = w4;
        kcur = knext;
    }
    {   // peeled last block
        float bm = fmaxf(fmaxf(fmaxf(max4(v0), max4(v1)),
                               fmaxf(max4(v2), max4(v3))), max4(v4));
        if (bm > best) { best = bm; kbest = kcur; }
    }

    // Recover exact element index: re-read winning block, first match wins.
    int bidx = 0;
    bool found = false;
#pragma unroll
    for (int u = 0; u < UNROLL; ++u) {
        float4 v = p[kbest + u * STRIDE];
        int base = (kbest + u * STRIDE) * 4;
        if (!found && v.x == best) { bidx = base;     found = true; }
        if (!found && v.y == best) { bidx = base + 1; found = true; }
        if (!found && v.z == best) { bidx = base + 2; found = true; }
        if (!found && v.w == best) { bidx = base + 3; found = true; }
    }

    // Pack (value, ~idx): u64 max == (max value, then smallest row index).
    unsigned long long key =
        ((unsigned long long)ford(best) << 32) |
        (unsigned long long)(0xFFFFFFFFu - (unsigned)bidx);

#pragma unroll
    for (int off = 16; off > 0; off >>= 1) {
        unsigned long long o = __shfl_down_sync(0xFFFFFFFFu, key, off);
        key = (o > key) ? o : key;
    }
    __shared__ unsigned long long s_key[NTHREADS / 32];
    __shared__ int s_last;
    __shared__ int s_not64;
    if ((threadIdx.x & 31) == 0) s_key[threadIdx.x >> 5] = key;
    __syncthreads();
    if (threadIdx.x == 0) {
        key = s_key[0];
#pragma unroll
        for (int w = 1; w < NTHREADS / 32; ++w)
            key = (s_key[w] > key) ? s_key[w] : key;
        g_part[blockIdx.x] = key;
        __threadfence();                        // release partial
        unsigned t = atomicAdd(&g_count, 1u);
        s_last = (t == (unsigned)(gridDim.x - 1));
        s_not64 = 0;
    }
    __syncthreads();
    if (!s_last) return;
    __threadfence();                            // acquire all partials

    // ---- rejection-sampling epilogue ----
    // Runtime input dtype detect: first 2048 B of draft exist under either
    // dtype; int64 => every high word is 0 (tokens < 128000).
    const unsigned long long* d64chk = (const unsigned long long*)draft_raw;
    for (int j = threadIdx.x; j < 256; j += NTHREADS)
        if (d64chk[j] >> 32) atomicOr(&s_not64, 1);
    __syncthreads();
    const bool is64 = (s_not64 == 0);

    const int b = threadIdx.x;
    if (b < BATCH) {
        const long long* draft64 = (const long long*)draft_raw;
        const int*       draft32 = (const int*)draft_raw;
        const long long* bonus64 = (const long long*)bonus_raw;
        const int*       bonus32 = (const int*)bonus_raw;

        int tgt[NSPEC];
        bool eq[NSPEC];
        int cum = 0;
#pragma unroll
        for (int s = 0; s < NSPEC; ++s) {
            const int r = b * NSPEC + s;
            unsigned long long k0 = g_part[2 * r];
            unsigned long long k1 = g_part[2 * r + 1];
            unsigned long long km = (k1 > k0) ? k1 : k0;
            tgt[s] = (int)(0xFFFFFFFFu - (unsigned)(km & 0xFFFFFFFFull));
            long long dv = is64 ? draft64[r] : (long long)draft32[r];
            cum += (dv == (long long)tgt[s]) ? 1 : 0;
            eq[s] = ((cum - 1) == s);           // drafts 0..s all matched
        }

        int sum_eq = 0;
#pragma unroll
        for (int s = 0; s < NSPEC; ++s) sum_eq += eq[s] ? 1 : 0;
        const int num_rejected = NSPEC - sum_eq;

        int first_diff = 0;                     // jnp.argmin: first False else 0
        bool any_false = false;
#pragma unroll
        for (int s = 0; s < NSPEC; ++s)
            if (!any_false && !eq[s]) { first_diff = s; any_false = true; }

        float outrow[NSPEC + 1];
        int keep_count = 0;
#pragma unroll
        for (int s = 0; s < NSPEC; ++s) {
            bool keep = (s <= first_diff) || eq[s];
            outrow[s] = keep ? (float)tgt[s] : -1.0f;
            keep_count += keep ? 1 : 0;
        }
        const bool last_all = eq[NSPEC - 1];
        long long bonus = is64 ? bonus64[b] : (long long)bonus32[b];
        outrow[NSPEC] = last_all ? (float)bonus : -1.0f;
        keep_count += last_all ? 1 : 0;

        const float last_tok = outrow[keep_count - 1];

        // Flattened tuple: [64*9 tokens | 64 num_rejected | 64 last_token]
#pragma unroll
        for (int s = 0; s <= NSPEC; ++s)
            out[b * (NSPEC + 1) + s] = outrow[s];
        out[BATCH * (NSPEC + 1) + b]         = (float)num_rejected;
        out[BATCH * (NSPEC + 1) + BATCH + b] = last_tok;
    }

    __syncthreads();
    if (threadIdx.x == 0) g_count = 0;          // reset for next graph replay
}

extern "C" void kernel_launch(void* const* d_in, const int* in_sizes, int n_in,
                              void* d_out, int out_size) {
    const float* logits = (const float*)d_in[0];   // [64, 8, 128000] fp32
    const void*  draft  = d_in[1];                 // [64, 8] int64 or int32
    const void*  bonus  = d_in[2];                 // [64, 1] int64 or int32
    (void)in_sizes; (void)n_in; (void)out_size;

    fused_kernel<<<NPART, NTHREADS>>>(logits, draft, bonus, (float*)d_out);
}